// round 10
// baseline (speedup 1.0000x reference)
#include <cuda_runtime.h>
#include <cuda_bf16.h>
#include <cstdint>

#define EPSF 1e-6f
#define TWO_PI_F 6.283185307179586f
#define NB_BASE 32
#define TPB 256

// Scratch (no device allocation allowed)
__device__ float g_ev[8192];       // per-event A_i * B_i
__device__ float g_base[NB_BASE];  // per-block base-rate partial sums
__device__ int   g_count = 0;      // arrival counter (reset by last block)

__device__ __forceinline__ uint32_t smem_u32(const void* p) {
    uint32_t a;
    asm("{ .reg .u64 tmp; cvta.to.shared.u64 tmp, %1; cvt.u32.u64 %0, tmp; }"
        : "=r"(a) : "l"(p));
    return a;
}

__device__ __forceinline__ void bulk_g2s(uint32_t smem_addr, const void* gptr,
                                         uint32_t bytes, uint32_t mbar_addr) {
    asm volatile(
        "cp.async.bulk.shared::cta.global.mbarrier::complete_tx::bytes "
        "[%0], [%1], %2, [%3];"
        :: "r"(smem_addr), "l"(gptr), "r"(bytes), "r"(mbar_addr) : "memory");
}

__device__ __forceinline__ void mbar_init(uint32_t mbar, uint32_t cnt) {
    asm volatile("mbarrier.init.shared.b64 [%0], %1;" :: "r"(mbar), "r"(cnt) : "memory");
}
__device__ __forceinline__ void mbar_expect_tx(uint32_t mbar, uint32_t bytes) {
    asm volatile("mbarrier.arrive.expect_tx.shared.b64 _, [%0], %1;"
                 :: "r"(mbar), "r"(bytes) : "memory");
}
__device__ __forceinline__ void mbar_wait(uint32_t mbar, uint32_t parity) {
    asm volatile(
        "{\n\t"
        ".reg .pred P1;\n\t"
        "WAIT_LOOP_%=:\n\t"
        "mbarrier.try_wait.parity.acquire.cta.shared::cta.b64 P1, [%0], %1, 0x989680;\n\t"
        "@P1 bra.uni WAIT_DONE_%=;\n\t"
        "bra.uni WAIT_LOOP_%=;\n\t"
        "WAIT_DONE_%=:\n\t"
        "}"
        :: "r"(mbar), "r"(parity) : "memory");
}

// ---------------------------------------------------------------------------
// Single fused kernel.
//   blocks [0, NB_BASE)             : base-rate grid partial sums
//   blocks [NB_BASE, NB_BASE + N)   : one event per block; past data pulled
//                                     into SMEM via cp.async.bulk (max MLP),
//                                     grid factors overlapped with the copy.
// Last block to arrive does the final deterministic reduction -> out[N].
// ---------------------------------------------------------------------------
__global__ __launch_bounds__(TPB, 6) void k_fused(
    const float* __restrict__ x, const float* __restrict__ t,
    const float* __restrict__ past_x, const float* __restrict__ past_t,
    const float* __restrict__ cov,
    const float* __restrict__ z, const float* __restrict__ x_grid,
    const float* __restrict__ t_grid, const float* __restrict__ beta,
    const float* __restrict__ p_alpha, const float* __restrict__ p_sigma,
    const float* __restrict__ p_omega,
    int N, int M, int G, int T, int D, int rows,
    float* __restrict__ out)
{
    __shared__ __align__(16) float sm_t[2048];   // 8 KB   (M=2048)
    __shared__ __align__(16) float sm_x[4096];   // 16 KB  (M=2048, 2 floats/pt)
    __shared__ __align__(8)  uint64_t sm_mbar;
    __shared__ float smS[8], smA[8], smB[8];
    __shared__ float sm_mu;
    __shared__ int   sm_last;

    const int tid  = threadIdx.x;
    const int warp = tid >> 5;
    const int lane = tid & 31;

    const float alpha = *p_alpha;
    const float sigma = *p_sigma;
    const float omega = *p_omega;
    const float inv2s2 = 1.0f / (2.0f * sigma * sigma);
    const float Cf     = alpha * omega / (TWO_PI_F * sigma * sigma);

    if (blockIdx.x < (unsigned)NB_BASE) {
        // ================= base-rate partial blocks =================
        const int bj = blockIdx.x;
        float bta[16];
        #pragma unroll
        for (int d = 0; d < 16; d++) bta[d] = (d < D) ? beta[d] : 0.0f;

        float s = 0.0f;
        if (D == 16) {
            for (int r = bj * TPB + tid; r < rows; r += NB_BASE * TPB) {
                const float4* __restrict__ zr =
                    reinterpret_cast<const float4*>(z + (size_t)r * 16);
                float4 v0 = zr[0], v1 = zr[1], v2 = zr[2], v3 = zr[3];
                float dot = 0.0f;
                dot = fmaf(v0.x, bta[0],  dot); dot = fmaf(v0.y, bta[1],  dot);
                dot = fmaf(v0.z, bta[2],  dot); dot = fmaf(v0.w, bta[3],  dot);
                dot = fmaf(v1.x, bta[4],  dot); dot = fmaf(v1.y, bta[5],  dot);
                dot = fmaf(v1.z, bta[6],  dot); dot = fmaf(v1.w, bta[7],  dot);
                dot = fmaf(v2.x, bta[8],  dot); dot = fmaf(v2.y, bta[9],  dot);
                dot = fmaf(v2.z, bta[10], dot); dot = fmaf(v2.w, bta[11], dot);
                dot = fmaf(v3.x, bta[12], dot); dot = fmaf(v3.y, bta[13], dot);
                dot = fmaf(v3.z, bta[14], dot); dot = fmaf(v3.w, bta[15], dot);
                s += fmaxf(dot, EPSF);
            }
        } else {
            for (int r = bj * TPB + tid; r < rows; r += NB_BASE * TPB) {
                float dot = 0.0f;
                for (int d = 0; d < D; d++)
                    dot = fmaf(z[(size_t)r * D + d], beta[d], dot);
                s += fmaxf(dot, EPSF);
            }
        }
        #pragma unroll
        for (int o = 16; o > 0; o >>= 1)
            s += __shfl_down_sync(0xffffffffu, s, o);
        if (lane == 0) smS[warp] = s;
        __syncthreads();
        if (tid == 0) {
            float S = 0.0f;
            #pragma unroll
            for (int w = 0; w < 8; w++) S += smS[w];
            g_base[bj] = S;
        }
    } else {
        // ================= event blocks (one event per block) =================
        const int i = blockIdx.x - NB_BASE;

        const float xi = x[2 * i];
        const float yi = x[2 * i + 1];
        const float ti = t[i];

        const bool fast = (M == 2048);
        const uint32_t mb = smem_u32(&sm_mbar);

        if (fast) {
            if (tid == 0) mbar_init(mb, 1);
            __syncthreads();
            if (tid == 0) {
                const uint32_t bytes_t = (uint32_t)M * 4u;
                const uint32_t bytes_x = (uint32_t)M * 8u;
                mbar_expect_tx(mb, bytes_t + bytes_x);
                bulk_g2s(smem_u32(sm_t), past_t + (size_t)i * M, bytes_t, mb);
                bulk_g2s(smem_u32(sm_x), past_x + (size_t)i * 2 * M, bytes_x, mb);
            }
        }

        // ---- overlap: grid factors + baseline while bulk copy in flight ----
        float a = 0.0f;
        const float2* __restrict__ gx = reinterpret_cast<const float2*>(x_grid);
        for (int g = tid; g < G; g += TPB) {
            float2 p  = gx[g];
            float  dx = p.x - xi;
            float  dy = p.y - yi;
            a += __expf(-(dx * dx + dy * dy) * inv2s2);
        }

        float b = 0.0f;
        for (int k = tid; k < T; k += TPB) {
            float dtau = t_grid[k] - ti;
            if (dtau > 0.0f)
                b += __expf(-omega * dtau);
        }

        float mu = 0.0f;
        if (tid < D)
            mu = cov[(size_t)i * D + tid] * beta[tid];

        // ---- excitation sum ----
        float s = 0.0f;
        if (fast) {
            mbar_wait(mb, 0);
            const float4* __restrict__ st4 = reinterpret_cast<const float4*>(sm_t);
            const float4* __restrict__ sx4 = reinterpret_cast<const float4*>(sm_x);
            #pragma unroll
            for (int half = 0; half < 2; half++) {
                const int sl = tid + half * TPB;     // 512 slots / 256 threads
                float4 tt = st4[sl];
                float4 p0 = sx4[2 * sl];
                float4 p1 = sx4[2 * sl + 1];
                float dt, dx, dy, r2, e;
                dt = ti - tt.x; dx = xi - p0.x; dy = yi - p0.y; r2 = dx*dx + dy*dy;
                e = __expf(-(r2 * inv2s2 + omega * dt)); s += (dt > 0.0f) ? e : 0.0f;
                dt = ti - tt.y; dx = xi - p0.z; dy = yi - p0.w; r2 = dx*dx + dy*dy;
                e = __expf(-(r2 * inv2s2 + omega * dt)); s += (dt > 0.0f) ? e : 0.0f;
                dt = ti - tt.z; dx = xi - p1.x; dy = yi - p1.y; r2 = dx*dx + dy*dy;
                e = __expf(-(r2 * inv2s2 + omega * dt)); s += (dt > 0.0f) ? e : 0.0f;
                dt = ti - tt.w; dx = xi - p1.z; dy = yi - p1.w; r2 = dx*dx + dy*dy;
                e = __expf(-(r2 * inv2s2 + omega * dt)); s += (dt > 0.0f) ? e : 0.0f;
            }
        } else {
            const float4* __restrict__ pt4 =
                reinterpret_cast<const float4*>(past_t + (size_t)i * M);
            const float4* __restrict__ px4 =
                reinterpret_cast<const float4*>(past_x + (size_t)i * 2 * M);
            for (int sl = tid; sl < M / 4; sl += TPB) {
                float4 tt = pt4[sl];
                float4 p0 = px4[2 * sl];
                float4 p1 = px4[2 * sl + 1];
                float dt, dx, dy, r2, e;
                dt = ti - tt.x; dx = xi - p0.x; dy = yi - p0.y; r2 = dx*dx + dy*dy;
                e = __expf(-(r2 * inv2s2 + omega * dt)); s += (dt > 0.0f) ? e : 0.0f;
                dt = ti - tt.y; dx = xi - p0.z; dy = yi - p0.w; r2 = dx*dx + dy*dy;
                e = __expf(-(r2 * inv2s2 + omega * dt)); s += (dt > 0.0f) ? e : 0.0f;
                dt = ti - tt.z; dx = xi - p1.x; dy = yi - p1.y; r2 = dx*dx + dy*dy;
                e = __expf(-(r2 * inv2s2 + omega * dt)); s += (dt > 0.0f) ? e : 0.0f;
                dt = ti - tt.w; dx = xi - p1.z; dy = yi - p1.w; r2 = dx*dx + dy*dy;
                e = __expf(-(r2 * inv2s2 + omega * dt)); s += (dt > 0.0f) ? e : 0.0f;
            }
        }

        // ---- deterministic block reduction (s, a, b, mu) ----
        #pragma unroll
        for (int o = 16; o > 0; o >>= 1) {
            s  += __shfl_down_sync(0xffffffffu, s,  o);
            a  += __shfl_down_sync(0xffffffffu, a,  o);
            b  += __shfl_down_sync(0xffffffffu, b,  o);
            mu += __shfl_down_sync(0xffffffffu, mu, o);
        }
        if (lane == 0) { smS[warp] = s; smA[warp] = a; smB[warp] = b; }
        if (tid == 0) sm_mu = mu;   // mu reduced within warp 0 (lanes [0,D))
        __syncthreads();

        if (tid == 0) {
            float S = 0.0f, A = 0.0f, B = 0.0f;
            #pragma unroll
            for (int w = 0; w < 8; w++) { S += smS[w]; A += smA[w]; B += smB[w]; }
            float m = fmaxf(sm_mu, EPSF);
            float lam = m + Cf * S;
            out[i]  = logf(lam + EPSF);
            g_ev[i] = A * B;
        }
    }

    // ================= last-block final reduction =================
    __syncthreads();
    if (tid == 0) {
        __threadfence();
        int prev = atomicAdd(&g_count, 1);
        sm_last = (prev == (int)gridDim.x - 1) ? 1 : 0;
    }
    __syncthreads();

    if (sm_last) {
        __threadfence();   // all partials visible

        float e = 0.0f;
        for (int i2 = tid; i2 < N; i2 += TPB) e += g_ev[i2];
        float b2 = (tid < NB_BASE) ? g_base[tid] : 0.0f;

        #pragma unroll
        for (int o = 16; o > 0; o >>= 1) {
            e  += __shfl_down_sync(0xffffffffu, e, o);
            b2 += __shfl_down_sync(0xffffffffu, b2, o);
        }
        if (lane == 0) { smS[warp] = e; smA[warp] = b2; }
        __syncthreads();

        if (tid == 0) {
            float E = 0.0f, B2 = 0.0f;
            #pragma unroll
            for (int w = 0; w < 8; w++) { E += smS[w]; B2 += smA[w]; }

            const float dt_step = t_grid[1] - t_grid[0];
            const float dxdy = 1.0f / (float)G;
            out[N] = (B2 + Cf * E) * dxdy * dt_step;

            g_count = 0;   // reset for next graph replay
        }
    }
}

// ---------------------------------------------------------------------------
extern "C" void kernel_launch(void* const* d_in, const int* in_sizes, int n_in,
                              void* d_out, int out_size)
{
    const float* x       = (const float*)d_in[0];
    const float* t       = (const float*)d_in[1];
    const float* past_x  = (const float*)d_in[2];
    const float* past_t  = (const float*)d_in[3];
    const float* cov     = (const float*)d_in[4];
    const float* z_grid  = (const float*)d_in[5];
    const float* x_grid  = (const float*)d_in[6];
    const float* t_grid  = (const float*)d_in[7];
    const float* beta    = (const float*)d_in[8];
    const float* p_alpha = (const float*)d_in[9];
    const float* p_sigma = (const float*)d_in[10];
    const float* p_omega = (const float*)d_in[11];
    float* out = (float*)d_out;

    const int N = in_sizes[1];
    const int M = in_sizes[3] / N;
    const int D = in_sizes[8];
    const int G = in_sizes[6] / 2;
    const int T = in_sizes[7];
    const int rows = in_sizes[5] / D;   // T*G

    k_fused<<<N + NB_BASE, TPB>>>(x, t, past_x, past_t, cov, z_grid, x_grid,
                                  t_grid, beta, p_alpha, p_sigma, p_omega,
                                  N, M, G, T, D, rows, out);
}

// round 11
// speedup vs baseline: 1.2541x; 1.2541x over previous
#include <cuda_runtime.h>
#include <cuda_bf16.h>

#define EPSF 1e-6f
#define TWO_PI_F 6.283185307179586f
#define NB_BASE 32
#define TPB 256

// ---------------------------------------------------------------------------
// Single fused kernel.
//   blocks [0, NB_BASE)           : base-rate grid partial sums -> RED out[N]
//   blocks [NB_BASE, NB_BASE + N) : one event per block:
//       out[i] = log(mu_i + Cf*S_i + eps)
//       RED out[N] += Cf * A_i * B_i * (dxdy * dt_step)
// out[N] is zeroed by a memset node before this kernel (graph-capturable).
// ---------------------------------------------------------------------------
__global__ __launch_bounds__(TPB) void k_fused(
    const float* __restrict__ x, const float* __restrict__ t,
    const float* __restrict__ past_x, const float* __restrict__ past_t,
    const float* __restrict__ cov,
    const float* __restrict__ z, const float* __restrict__ x_grid,
    const float* __restrict__ t_grid, const float* __restrict__ beta,
    const float* __restrict__ p_alpha, const float* __restrict__ p_sigma,
    const float* __restrict__ p_omega,
    int N, int M, int G, int T, int D, int rows,
    float* __restrict__ out)
{
    __shared__ float smS[8], smA[8], smB[8];
    __shared__ float sm_mu;
    const int tid  = threadIdx.x;
    const int warp = tid >> 5;
    const int lane = tid & 31;

    const float alpha = *p_alpha;
    const float sigma = *p_sigma;
    const float omega = *p_omega;
    const float inv2s2 = 1.0f / (2.0f * sigma * sigma);
    const float Cf     = alpha * omega / (TWO_PI_F * sigma * sigma);
    const float dt_step = t_grid[1] - t_grid[0];
    const float scale   = dt_step / (float)G;    // dxdy * dt_step

    if (blockIdx.x < (unsigned)NB_BASE) {
        // ================= base-rate partial blocks =================
        const int bj = blockIdx.x;
        float bta[16];
        #pragma unroll
        for (int d = 0; d < 16; d++) bta[d] = (d < D) ? beta[d] : 0.0f;

        float s = 0.0f;
        if (D == 16) {
            for (int r = bj * TPB + tid; r < rows; r += NB_BASE * TPB) {
                const float4* __restrict__ zr =
                    reinterpret_cast<const float4*>(z + (size_t)r * 16);
                float4 v0 = zr[0], v1 = zr[1], v2 = zr[2], v3 = zr[3];
                float dot = 0.0f;
                dot = fmaf(v0.x, bta[0],  dot); dot = fmaf(v0.y, bta[1],  dot);
                dot = fmaf(v0.z, bta[2],  dot); dot = fmaf(v0.w, bta[3],  dot);
                dot = fmaf(v1.x, bta[4],  dot); dot = fmaf(v1.y, bta[5],  dot);
                dot = fmaf(v1.z, bta[6],  dot); dot = fmaf(v1.w, bta[7],  dot);
                dot = fmaf(v2.x, bta[8],  dot); dot = fmaf(v2.y, bta[9],  dot);
                dot = fmaf(v2.z, bta[10], dot); dot = fmaf(v2.w, bta[11], dot);
                dot = fmaf(v3.x, bta[12], dot); dot = fmaf(v3.y, bta[13], dot);
                dot = fmaf(v3.z, bta[14], dot); dot = fmaf(v3.w, bta[15], dot);
                s += fmaxf(dot, EPSF);
            }
        } else {
            for (int r = bj * TPB + tid; r < rows; r += NB_BASE * TPB) {
                float dot = 0.0f;
                for (int d = 0; d < D; d++)
                    dot = fmaf(z[(size_t)r * D + d], beta[d], dot);
                s += fmaxf(dot, EPSF);
            }
        }
        #pragma unroll
        for (int o = 16; o > 0; o >>= 1)
            s += __shfl_down_sync(0xffffffffu, s, o);
        if (lane == 0) smS[warp] = s;
        __syncthreads();
        if (tid == 0) {
            float S = 0.0f;
            #pragma unroll
            for (int w = 0; w < 8; w++) S += smS[w];
            atomicAdd(out + N, S * scale);
        }
    } else {
        // ================= event blocks (one event per block) =================
        const int i = blockIdx.x - NB_BASE;

        const float xi = x[2 * i];
        const float yi = x[2 * i + 1];
        const float ti = t[i];

        const float4* __restrict__ pt4 =
            reinterpret_cast<const float4*>(past_t + (size_t)i * M);
        const float4* __restrict__ px4 =
            reinterpret_cast<const float4*>(past_x + (size_t)i * 2 * M);

        float s = 0.0f;

        if (M == 2048) {
            // Front-batched: 6 independent LDG.128 in flight before compute.
            const int s0 = tid;
            const int s1 = tid + 256;
            float4 tt0 = pt4[s0];
            float4 tt1 = pt4[s1];
            float4 a0  = px4[2 * s0];
            float4 a1  = px4[2 * s0 + 1];
            float4 b0  = px4[2 * s1];
            float4 b1  = px4[2 * s1 + 1];

            float dt, dx, dy, r2, e;
            dt = ti - tt0.x; dx = xi - a0.x; dy = yi - a0.y; r2 = dx*dx + dy*dy;
            e = __expf(-(r2 * inv2s2 + omega * dt)); s += (dt > 0.0f) ? e : 0.0f;
            dt = ti - tt0.y; dx = xi - a0.z; dy = yi - a0.w; r2 = dx*dx + dy*dy;
            e = __expf(-(r2 * inv2s2 + omega * dt)); s += (dt > 0.0f) ? e : 0.0f;
            dt = ti - tt0.z; dx = xi - a1.x; dy = yi - a1.y; r2 = dx*dx + dy*dy;
            e = __expf(-(r2 * inv2s2 + omega * dt)); s += (dt > 0.0f) ? e : 0.0f;
            dt = ti - tt0.w; dx = xi - a1.z; dy = yi - a1.w; r2 = dx*dx + dy*dy;
            e = __expf(-(r2 * inv2s2 + omega * dt)); s += (dt > 0.0f) ? e : 0.0f;
            dt = ti - tt1.x; dx = xi - b0.x; dy = yi - b0.y; r2 = dx*dx + dy*dy;
            e = __expf(-(r2 * inv2s2 + omega * dt)); s += (dt > 0.0f) ? e : 0.0f;
            dt = ti - tt1.y; dx = xi - b0.z; dy = yi - b0.w; r2 = dx*dx + dy*dy;
            e = __expf(-(r2 * inv2s2 + omega * dt)); s += (dt > 0.0f) ? e : 0.0f;
            dt = ti - tt1.z; dx = xi - b1.x; dy = yi - b1.y; r2 = dx*dx + dy*dy;
            e = __expf(-(r2 * inv2s2 + omega * dt)); s += (dt > 0.0f) ? e : 0.0f;
            dt = ti - tt1.w; dx = xi - b1.z; dy = yi - b1.w; r2 = dx*dx + dy*dy;
            e = __expf(-(r2 * inv2s2 + omega * dt)); s += (dt > 0.0f) ? e : 0.0f;
        } else {
            for (int sl = tid; sl < M / 4; sl += TPB) {
                float4 tt = pt4[sl];
                float4 p0 = px4[2 * sl];
                float4 p1 = px4[2 * sl + 1];
                float dt, dx, dy, r2, e;
                dt = ti - tt.x; dx = xi - p0.x; dy = yi - p0.y; r2 = dx*dx + dy*dy;
                e = __expf(-(r2 * inv2s2 + omega * dt)); s += (dt > 0.0f) ? e : 0.0f;
                dt = ti - tt.y; dx = xi - p0.z; dy = yi - p0.w; r2 = dx*dx + dy*dy;
                e = __expf(-(r2 * inv2s2 + omega * dt)); s += (dt > 0.0f) ? e : 0.0f;
                dt = ti - tt.z; dx = xi - p1.x; dy = yi - p1.y; r2 = dx*dx + dy*dy;
                e = __expf(-(r2 * inv2s2 + omega * dt)); s += (dt > 0.0f) ? e : 0.0f;
                dt = ti - tt.w; dx = xi - p1.z; dy = yi - p1.w; r2 = dx*dx + dy*dy;
                e = __expf(-(r2 * inv2s2 + omega * dt)); s += (dt > 0.0f) ? e : 0.0f;
            }
        }

        // ---- spatial grid factor A_i ----
        float a = 0.0f;
        const float2* __restrict__ gx = reinterpret_cast<const float2*>(x_grid);
        for (int g = tid; g < G; g += TPB) {
            float2 p  = gx[g];
            float  dx = p.x - xi;
            float  dy = p.y - yi;
            a += __expf(-(dx * dx + dy * dy) * inv2s2);
        }

        // ---- temporal grid factor B_i ----
        float b = 0.0f;
        for (int k = tid; k < T; k += TPB) {
            float dtau = t_grid[k] - ti;
            if (dtau > 0.0f)
                b += __expf(-omega * dtau);
        }

        // ---- baseline partial: threads [0, D) (all in warp 0) ----
        float mu = 0.0f;
        if (tid < D)
            mu = cov[(size_t)i * D + tid] * beta[tid];

        // ---- deterministic block reduction (s, a, b, mu) ----
        #pragma unroll
        for (int o = 16; o > 0; o >>= 1) {
            s  += __shfl_down_sync(0xffffffffu, s,  o);
            a  += __shfl_down_sync(0xffffffffu, a,  o);
            b  += __shfl_down_sync(0xffffffffu, b,  o);
            mu += __shfl_down_sync(0xffffffffu, mu, o);
        }
        if (lane == 0) { smS[warp] = s; smA[warp] = a; smB[warp] = b; }
        if (tid == 0) sm_mu = mu;
        __syncthreads();

        if (tid == 0) {
            float S = 0.0f, A = 0.0f, B = 0.0f;
            #pragma unroll
            for (int w = 0; w < 8; w++) { S += smS[w]; A += smA[w]; B += smB[w]; }
            float m = fmaxf(sm_mu, EPSF);
            float lam = m + Cf * S;
            out[i] = logf(lam + EPSF);
            atomicAdd(out + N, Cf * A * B * scale);
        }
    }
}

// ---------------------------------------------------------------------------
extern "C" void kernel_launch(void* const* d_in, const int* in_sizes, int n_in,
                              void* d_out, int out_size)
{
    const float* x       = (const float*)d_in[0];
    const float* t       = (const float*)d_in[1];
    const float* past_x  = (const float*)d_in[2];
    const float* past_t  = (const float*)d_in[3];
    const float* cov     = (const float*)d_in[4];
    const float* z_grid  = (const float*)d_in[5];
    const float* x_grid  = (const float*)d_in[6];
    const float* t_grid  = (const float*)d_in[7];
    const float* beta    = (const float*)d_in[8];
    const float* p_alpha = (const float*)d_in[9];
    const float* p_sigma = (const float*)d_in[10];
    const float* p_omega = (const float*)d_in[11];
    float* out = (float*)d_out;

    const int N = in_sizes[1];
    const int M = in_sizes[3] / N;
    const int D = in_sizes[8];
    const int G = in_sizes[6] / 2;
    const int T = in_sizes[7];
    const int rows = in_sizes[5] / D;   // T*G

    // Zero the integral accumulator (graph-capturable memset node).
    cudaMemsetAsync(out + N, 0, sizeof(float));

    k_fused<<<N + NB_BASE, TPB>>>(x, t, past_x, past_t, cov, z_grid, x_grid,
                                  t_grid, beta, p_alpha, p_sigma, p_omega,
                                  N, M, G, T, D, rows, out);
}